// round 1
// baseline (speedup 1.0000x reference)
#include <cuda_runtime.h>

#define NPTS 4096
#define CCH  128
#define GG   49
#define PAD  132        // smem row stride (floats): 16B-aligned, conflict-mitigating
#define MROWS 16384     // 4 levels * 4096 points

// ---- scratch (static device globals: allocation-free at launch time) ----
__device__ float g_fmapt[2088960];                 // fmaps transposed to [H,W,C], 4 levels
__device__ float g_X[(size_t)MROWS * 2401];        // correlation volumes (MLP1 input)
__device__ float g_H[(size_t)MROWS * 384];         // MLP1 activations

// ============================================================
// Kernel 0: transpose fmap [C,H,W] -> [H,W,C] (small, one-shot)
// ============================================================
__global__ void k_transpose(const float* __restrict__ in, int HW, int outOff) {
  int p = blockIdx.x;
  int c = threadIdx.x;
  g_fmapt[(size_t)outOff + (size_t)p * CCH + c] = in[(size_t)c * HW + p];
}

// ============================================================
// Kernel 1: per (level, point): bilinear 7x7xC gather + 49x49x128 corr GEMM
// grid = NPTS blocks, 256 threads. dyn smem = 2*GG*PAD*4 = 51744 B
// ============================================================
__global__ __launch_bounds__(256) void k_corr(
    const float* __restrict__ tfeat,   // [49, N, 128]
    const float* __restrict__ coords,  // [N, 2]
    int H, int W, int fmOff, int level, float scale)
{
  extern __shared__ float sm[];
  float* tmpl_s = sm;                // [49][PAD]
  float* cf_s   = sm + GG * PAD;     // [49][PAD]
  const float* fmap = g_fmapt + fmOff;   // [H,W,C]
  const int n = blockIdx.x;
  const int tid = threadIdx.x;

  // --- load template support features (coalesced along C) ---
  for (int idx = tid; idx < GG * CCH; idx += 256) {
    int t = idx >> 7, c = idx & 127;
    tmpl_s[t * PAD + c] = tfeat[(size_t)t * (NPTS * CCH) + (size_t)n * CCH + c];
  }

  float cx = coords[2 * n]     * scale;
  float cy = coords[2 * n + 1] * scale;

  // --- bilinear gather: corr_feat[p][c] with p=(gi*7+gj), x+=off[gi], y+=off[gj] ---
  {
    int c    = tid & 127;
    int half = tid >> 7;
    for (int p = half; p < GG; p += 2) {
      int gi = p / 7, gj = p - gi * 7;
      float xs = cx + (float)(gi - 3);
      float ys = cy + (float)(gj - 3);
      float x0f = floorf(xs), y0f = floorf(ys);
      float wx = xs - x0f, wy = ys - y0f;
      int x0 = (int)x0f, y0 = (int)y0f;
      float w00 = (1.f - wy) * (1.f - wx);
      float w01 = (1.f - wy) * wx;
      float w10 = wy * (1.f - wx);
      float w11 = wy * wx;
      float v = 0.f;
      bool xin0 = (x0 >= 0) && (x0 < W);
      bool xin1 = (x0 + 1 >= 0) && (x0 + 1 < W);
      if (y0 >= 0 && y0 < H) {
        size_t rb = (size_t)y0 * W;
        if (xin0) v += w00 * fmap[(rb + x0) * CCH + c];
        if (xin1) v += w01 * fmap[(rb + x0 + 1) * CCH + c];
      }
      if (y0 + 1 >= 0 && y0 + 1 < H) {
        size_t rb = (size_t)(y0 + 1) * W;
        if (xin0) v += w10 * fmap[(rb + x0) * CCH + c];
        if (xin1) v += w11 * fmap[(rb + x0 + 1) * CCH + c];
      }
      cf_s[p * PAD + c] = v;
    }
  }
  __syncthreads();

  // --- 49x49 GEMM over C=128: 4x4 register tile per thread (16x16 threads) ---
  int tx = tid & 15, ty = tid >> 4;
  float acc[4][4];
#pragma unroll
  for (int a = 0; a < 4; a++)
#pragma unroll
    for (int b = 0; b < 4; b++) acc[a][b] = 0.f;

  int hw[4], ij[4];
#pragma unroll
  for (int a = 0; a < 4; a++) {
    int h = ty + 16 * a; hw[a] = (h > 48) ? 48 : h;
    int j = tx + 16 * a; ij[a] = (j > 48) ? 48 : j;
  }

#pragma unroll 4
  for (int cc = 0; cc < CCH; cc += 4) {
    float4 av[4], bv[4];
#pragma unroll
    for (int a = 0; a < 4; a++) av[a] = *(const float4*)&cf_s[hw[a] * PAD + cc];
#pragma unroll
    for (int b = 0; b < 4; b++) bv[b] = *(const float4*)&tmpl_s[ij[b] * PAD + cc];
#pragma unroll
    for (int a = 0; a < 4; a++)
#pragma unroll
      for (int b = 0; b < 4; b++) {
        acc[a][b] += av[a].x * bv[b].x;
        acc[a][b] += av[a].y * bv[b].y;
        acc[a][b] += av[a].z * bv[b].z;
        acc[a][b] += av[a].w * bv[b].w;
      }
  }

  size_t rowbase = ((size_t)level * NPTS + n) * 2401;
#pragma unroll
  for (int a = 0; a < 4; a++)
#pragma unroll
    for (int b = 0; b < 4; b++)
      if ((ty + 16 * a) < GG && (tx + 16 * b) < GG)
        g_X[rowbase + (size_t)hw[a] * GG + ij[b]] = acc[a][b];
}

// ============================================================
// Kernel 2: H = gelu_exact(X @ w1 + b1)   M=16384, K=2401, N=384
// BM=128 BN=64 BK=16, 256 thr, 8x4 microtile. grid = (N/BN, M/BM)
// ============================================================
#define BM 128
#define BN 64
#define BK 16

__global__ __launch_bounds__(256) void k_mlp1(const float* __restrict__ Bw,
                                              const float* __restrict__ bias) {
  __shared__ float As[BK][BM + 4];
  __shared__ float Bs[BK][BN];
  const int K = 2401, Nn = 384;
  int tid = threadIdx.x;
  int tx = tid & 15, ty = tid >> 4;
  int col0 = blockIdx.x * BN;
  int row0 = blockIdx.y * BM;

  float acc[8][4];
#pragma unroll
  for (int i = 0; i < 8; i++)
#pragma unroll
    for (int j = 0; j < 4; j++) acc[i][j] = 0.f;

  for (int k0 = 0; k0 < K; k0 += BK) {
#pragma unroll
    for (int i = 0; i < 8; i++) {
      int idx = tid + i * 256;
      int m = idx >> 4, kk = idx & 15;
      int gk = k0 + kk;
      As[kk][m] = (gk < K) ? g_X[(size_t)(row0 + m) * K + gk] : 0.f;
    }
#pragma unroll
    for (int i = 0; i < 4; i++) {
      int idx = tid + i * 256;
      int kk = idx >> 6, j = idx & 63;
      int gk = k0 + kk;
      Bs[kk][j] = (gk < K) ? Bw[(size_t)gk * Nn + col0 + j] : 0.f;
    }
    __syncthreads();
#pragma unroll
    for (int kk = 0; kk < BK; kk++) {
      float4 a0 = *(const float4*)&As[kk][ty * 8];
      float4 a1 = *(const float4*)&As[kk][ty * 8 + 4];
      float4 b0 = *(const float4*)&Bs[kk][tx * 4];
      float a[8] = {a0.x, a0.y, a0.z, a0.w, a1.x, a1.y, a1.z, a1.w};
      float b[4] = {b0.x, b0.y, b0.z, b0.w};
#pragma unroll
      for (int i = 0; i < 8; i++)
#pragma unroll
        for (int j = 0; j < 4; j++) acc[i][j] += a[i] * b[j];
    }
    __syncthreads();
  }

#pragma unroll
  for (int i = 0; i < 8; i++)
#pragma unroll
    for (int j = 0; j < 4; j++) {
      int m = row0 + ty * 8 + i;
      int jg = col0 + tx * 4 + j;
      float v = acc[i][j] + bias[jg];
      // exact GELU: 0.5*v*(1+erf(v/sqrt(2)))
      g_H[(size_t)m * 384 + jg] = 0.5f * v * (1.f + erff(v * 0.70710678118654752f));
    }
}

// ============================================================
// Kernel 3: out = H @ w2 + b2, scattered into concat layout
// M=16384, K=384, N=256. row r -> out[(r&4095)*1024 + (r>>12)*256 + j]
// ============================================================
__global__ __launch_bounds__(256) void k_mlp2(const float* __restrict__ Bw,
                                              const float* __restrict__ bias,
                                              float* __restrict__ out) {
  __shared__ float As[BK][BM + 4];
  __shared__ float Bs[BK][BN];
  const int K = 384, Nn = 256;
  int tid = threadIdx.x;
  int tx = tid & 15, ty = tid >> 4;
  int col0 = blockIdx.x * BN;
  int row0 = blockIdx.y * BM;

  float acc[8][4];
#pragma unroll
  for (int i = 0; i < 8; i++)
#pragma unroll
    for (int j = 0; j < 4; j++) acc[i][j] = 0.f;

  for (int k0 = 0; k0 < K; k0 += BK) {
#pragma unroll
    for (int i = 0; i < 8; i++) {
      int idx = tid + i * 256;
      int m = idx >> 4, kk = idx & 15;
      As[kk][m] = g_H[(size_t)(row0 + m) * K + k0 + kk];
    }
#pragma unroll
    for (int i = 0; i < 4; i++) {
      int idx = tid + i * 256;
      int kk = idx >> 6, j = idx & 63;
      Bs[kk][j] = Bw[(size_t)(k0 + kk) * Nn + col0 + j];
    }
    __syncthreads();
#pragma unroll
    for (int kk = 0; kk < BK; kk++) {
      float4 a0 = *(const float4*)&As[kk][ty * 8];
      float4 a1 = *(const float4*)&As[kk][ty * 8 + 4];
      float4 b0 = *(const float4*)&Bs[kk][tx * 4];
      float a[8] = {a0.x, a0.y, a0.z, a0.w, a1.x, a1.y, a1.z, a1.w};
      float b[4] = {b0.x, b0.y, b0.z, b0.w};
#pragma unroll
      for (int i = 0; i < 8; i++)
#pragma unroll
        for (int j = 0; j < 4; j++) acc[i][j] += a[i] * b[j];
    }
    __syncthreads();
  }

#pragma unroll
  for (int i = 0; i < 8; i++)
#pragma unroll
    for (int j = 0; j < 4; j++) {
      int m = row0 + ty * 8 + i;
      int lev = m >> 12;
      int npt = m & 4095;
      int jg = col0 + tx * 4 + j;
      out[(size_t)npt * 1024 + lev * 256 + jg] = acc[i][j] + bias[jg];
    }
}

// ============================================================
// Launch
// ============================================================
extern "C" void kernel_launch(void* const* d_in, const int* in_sizes, int n_in,
                              void* d_out, int out_size) {
  // Robust input mapping by element count (handles either dict or signature order;
  // 98304 is ambiguous between fmaps2 and w2 — fmaps2 comes first in both orders).
  const float* fm[4] = {0, 0, 0, 0};
  const float* tf[4] = {0, 0, 0, 0};
  const float* coords = 0;
  const float* w1 = 0; const float* b1 = 0;
  const float* w2 = 0; const float* b2 = 0;
  int tfi = 0, seen98304 = 0;
  for (int i = 0; i < n_in; i++) {
    const float* p = (const float*)d_in[i];
    switch (in_sizes[i]) {
      case 1572864:  fm[0] = p; break;
      case 393216:   fm[1] = p; break;
      case 98304:    if (!seen98304) { fm[2] = p; seen98304 = 1; } else w2 = p; break;
      case 24576:    fm[3] = p; break;
      case 25690112: if (tfi < 4) tf[tfi++] = p; break;
      case 8192:     coords = p; break;
      case 921984:   w1 = p; break;
      case 384:      b1 = p; break;
      case 256:      b2 = p; break;
      default: break;
    }
  }

  static const int Hs[4]   = {96, 48, 24, 12};
  static const int Ws[4]   = {128, 64, 32, 16};
  static const int offs[4] = {0, 1572864, 1966080, 2064384};

  for (int l = 0; l < 4; l++)
    k_transpose<<<Hs[l] * Ws[l], 128>>>(fm[l], Hs[l] * Ws[l], offs[l]);

  const int corrSmem = 2 * GG * PAD * 4;  // 51744 B > 48K default
  cudaFuncSetAttribute(k_corr, cudaFuncAttributeMaxDynamicSharedMemorySize, corrSmem);
  for (int l = 0; l < 4; l++) {
    float scale = 1.f / (float)(1 << l);
    k_corr<<<NPTS, 256, corrSmem>>>(tf[l], coords, Hs[l], Ws[l], offs[l], l, scale);
  }

  k_mlp1<<<dim3(384 / BN, MROWS / BM), 256>>>(w1, b1);
  k_mlp2<<<dim3(256 / BN, MROWS / BM), 256>>>(w2, b2, (float*)d_out);
}